// round 1
// baseline (speedup 1.0000x reference)
#include <cuda_runtime.h>
#include <math.h>

// GWNN: N=8192, F_IN=512, H=256, O=64
//   t = x @ w1                       [N,H]
//   u = (Winv @ t) * f1[:,None]      [N,H]   (rowscale fused in epilogue)
//   h = relu(W @ u)                  [N,H]   (relu fused in epilogue)
//   s = h @ w2                       [N,O]
//   v = (Winv @ s) * f2[:,None]      [N,O]
//   o = W @ v                        [N,O]
//   out = log_softmax(o, axis=1)

#define NR   8192
#define FIN  512
#define HID  256
#define OUTD 64

// Scratch (device globals; no allocation allowed in kernel_launch)
__device__ float g_t[NR * HID];
__device__ float g_u[NR * HID];
__device__ float g_h[NR * HID];
__device__ float g_s[NR * OUTD];
__device__ float g_v[NR * OUTD];
__device__ float g_o[NR * OUTD];

// ---------------------------------------------------------------------------
// Tiled fp32 SGEMM: C[M,Nc] = A[M,K] @ B[K,Nc], row-major, all dims aligned.
// BM=128, BN=64, BK=16, 256 threads, 8x4 microtile per thread.
// EPI: 0 = none, 1 = C[i,:] *= rowscale[i], 2 = relu
// ---------------------------------------------------------------------------
template <int EPI>
__global__ __launch_bounds__(256)
void sgemm_kernel(const float* __restrict__ A, const float* __restrict__ B,
                  float* __restrict__ C, int M, int Nc, int K,
                  const float* __restrict__ rowscale)
{
    constexpr int BM = 128, BN = 64, BK = 16;
    __shared__ float As[BK][BM];   // transposed A tile: As[k][m]
    __shared__ float Bs[BK][BN];   // Bs[k][n]

    const int tid = threadIdx.x;
    const int bm  = blockIdx.y * BM;
    const int bn  = blockIdx.x * BN;

    // compute-thread microtile coordinates
    const int trow = (tid / 16) * 8;   // 0..120
    const int tcol = (tid % 16) * 4;   // 0..60

    // loader coordinates
    const int arow = tid >> 1;         // 0..127
    const int acol = (tid & 1) * 8;    // 0 or 8 (two float4 along K)
    const int brow = tid >> 4;         // 0..15
    const int bcol = (tid & 15) * 4;   // 0..60

    const float* Aptr = A + (size_t)(bm + arow) * K + acol;
    const float* Bptr = B + (size_t)brow * Nc + bn + bcol;

    float acc[8][4];
#pragma unroll
    for (int i = 0; i < 8; i++)
#pragma unroll
        for (int j = 0; j < 4; j++) acc[i][j] = 0.0f;

    for (int k0 = 0; k0 < K; k0 += BK) {
        // global -> shared
        float4 a0 = *(const float4*)(Aptr + k0);
        float4 a1 = *(const float4*)(Aptr + k0 + 4);
        float4 b  = *(const float4*)(Bptr + (size_t)k0 * Nc);

        As[acol + 0][arow] = a0.x;
        As[acol + 1][arow] = a0.y;
        As[acol + 2][arow] = a0.z;
        As[acol + 3][arow] = a0.w;
        As[acol + 4][arow] = a1.x;
        As[acol + 5][arow] = a1.y;
        As[acol + 6][arow] = a1.z;
        As[acol + 7][arow] = a1.w;
        *(float4*)&Bs[brow][bcol] = b;
        __syncthreads();

#pragma unroll
        for (int kk = 0; kk < BK; kk++) {
            float4 av0 = *(const float4*)&As[kk][trow];
            float4 av1 = *(const float4*)&As[kk][trow + 4];
            float4 bv  = *(const float4*)&Bs[kk][tcol];
            float a_[8] = {av0.x, av0.y, av0.z, av0.w, av1.x, av1.y, av1.z, av1.w};
            float b_[4] = {bv.x, bv.y, bv.z, bv.w};
#pragma unroll
            for (int i = 0; i < 8; i++)
#pragma unroll
                for (int j = 0; j < 4; j++)
                    acc[i][j] = fmaf(a_[i], b_[j], acc[i][j]);
        }
        __syncthreads();
    }

    // epilogue
#pragma unroll
    for (int i = 0; i < 8; i++) {
        const int row = bm + trow + i;
        float sc = 1.0f;
        if (EPI == 1) sc = rowscale[row];
        float4 o4;
        float* po = (float*)&o4;
#pragma unroll
        for (int j = 0; j < 4; j++) {
            float v = acc[i][j];
            if (EPI == 1) v *= sc;
            if (EPI == 2) v = fmaxf(v, 0.0f);
            po[j] = v;
        }
        *(float4*)&C[(size_t)row * Nc + bn + tcol] = o4;
    }
}

// ---------------------------------------------------------------------------
// log_softmax over rows of 64 (one warp per row)
// ---------------------------------------------------------------------------
__global__ __launch_bounds__(256)
void logsoftmax64_kernel(const float* __restrict__ in, float* __restrict__ out)
{
    const int warp = (blockIdx.x * blockDim.x + threadIdx.x) >> 5;
    const int lane = threadIdx.x & 31;
    if (warp >= NR) return;

    const float* r = in + (size_t)warp * OUTD;
    float v0 = r[lane];
    float v1 = r[lane + 32];

    float m = fmaxf(v0, v1);
#pragma unroll
    for (int o = 16; o > 0; o >>= 1)
        m = fmaxf(m, __shfl_xor_sync(0xFFFFFFFFu, m, o));

    float s = expf(v0 - m) + expf(v1 - m);
#pragma unroll
    for (int o = 16; o > 0; o >>= 1)
        s += __shfl_xor_sync(0xFFFFFFFFu, s, o);

    const float lse = m + logf(s);
    out[(size_t)warp * OUTD + lane]      = v0 - lse;
    out[(size_t)warp * OUTD + lane + 32] = v1 - lse;
}

// ---------------------------------------------------------------------------
// kernel_launch — graph-capturable, allocation-free
// Inputs (metadata order): x, wavelets, wavelets_inv, w1, f1, w2, f2
// ---------------------------------------------------------------------------
extern "C" void kernel_launch(void* const* d_in, const int* in_sizes, int n_in,
                              void* d_out, int out_size)
{
    (void)in_sizes; (void)n_in; (void)out_size;
    const float* x    = (const float*)d_in[0];
    const float* W    = (const float*)d_in[1];
    const float* Winv = (const float*)d_in[2];
    const float* w1   = (const float*)d_in[3];
    const float* f1   = (const float*)d_in[4];
    const float* w2   = (const float*)d_in[5];
    const float* f2   = (const float*)d_in[6];
    float* out = (float*)d_out;

    float *t, *u, *h, *s, *v, *o;
    cudaGetSymbolAddress((void**)&t, g_t);
    cudaGetSymbolAddress((void**)&u, g_u);
    cudaGetSymbolAddress((void**)&h, g_h);
    cudaGetSymbolAddress((void**)&s, g_s);
    cudaGetSymbolAddress((void**)&v, g_v);
    cudaGetSymbolAddress((void**)&o, g_o);

    const dim3 blk(256);
    const dim3 gridH(HID / 64, NR / 128);   // N=256 outputs
    const dim3 gridO(OUTD / 64, NR / 128);  // N=64 outputs

    // Layer 1
    sgemm_kernel<0><<<gridH, blk>>>(x,    w1, t, NR, HID, FIN, nullptr);  // t = x @ w1
    sgemm_kernel<1><<<gridH, blk>>>(Winv, t,  u, NR, HID, NR,  f1);      // u = (Winv@t)*f1
    sgemm_kernel<2><<<gridH, blk>>>(W,    u,  h, NR, HID, NR,  nullptr); // h = relu(W@u)
    // Layer 2
    sgemm_kernel<0><<<gridO, blk>>>(h,    w2, s, NR, OUTD, HID, nullptr); // s = h @ w2
    sgemm_kernel<1><<<gridO, blk>>>(Winv, s,  v, NR, OUTD, NR,  f2);      // v = (Winv@s)*f2
    sgemm_kernel<0><<<gridO, blk>>>(W,    v,  o, NR, OUTD, NR,  nullptr); // o = W @ v

    // out = log_softmax(o, axis=1)
    logsoftmax64_kernel<<<(NR * 32) / 256, blk>>>(o, out);
}

// round 3
// speedup vs baseline: 3.5531x; 3.5531x over previous
#include <cuda_runtime.h>
#include <cstdint>
#include <math.h>

// GWNN on GB300 — mma.sync tf32 path (tcgen05 unavailable: harness PTX target
// is compute_103, which rejects arch-suffix instructions).
//
// Feature-major intermediates: X^T is [d, 8192].
//   tT = w1T (x) x        K=512
//   uT = tT  (x) Winv     K=8192, *f1[col]
//   hT = relu(uT (x) W)   K=8192
//   sT = w2T @ hT         K=256 (SIMT, rows 0..63; 64..127 stay zero)
//   vT = sT  (x) Winv     K=8192, *f2[col]   (padded M=128)
//   oT = vT  (x) W        K=8192             (padded M=128)
//   out[m,j] = oT[j,m] - logsumexp_j

#define NR   8192
#define FIN  512
#define HID  256
#define OUTD 64

__device__ float g_w1T[HID * FIN];
__device__ float g_tT [HID * NR];
__device__ float g_uT [HID * NR];
__device__ float g_hT [HID * NR];
__device__ float g_sT [128 * NR];   // rows 64..127 permanently zero
__device__ float g_vT [128 * NR];
__device__ float g_oT [128 * NR];

// ---------------- PTX helpers ----------------------------------------------
__device__ __forceinline__ uint32_t smem_u32(const void* p) {
    uint32_t a;
    asm("{ .reg .u64 t; cvta.to.shared.u64 t, %1; cvt.u32.u64 %0, t; }" : "=r"(a) : "l"(p));
    return a;
}
#define SWZ(x) ((x) ^ (((x) >> 3) & 0x70))

__device__ __forceinline__ void cp_async16(uint32_t dst, const void* src) {
    asm volatile("cp.async.cg.shared.global [%0], [%1], 16;" :: "r"(dst), "l"(src));
}
__device__ __forceinline__ void cp_commit() {
    asm volatile("cp.async.commit_group;" ::: "memory");
}
template <int N>
__device__ __forceinline__ void cp_wait() {
    asm volatile("cp.async.wait_group %0;" :: "n"(N) : "memory");
}
__device__ __forceinline__ void ldsm_x4(uint32_t& r0, uint32_t& r1, uint32_t& r2, uint32_t& r3,
                                        uint32_t addr) {
    asm volatile("ldmatrix.sync.aligned.m8n8.x4.shared.b16 {%0,%1,%2,%3}, [%4];"
                 : "=r"(r0), "=r"(r1), "=r"(r2), "=r"(r3) : "r"(addr));
}
__device__ __forceinline__ uint32_t f2tf32(uint32_t x) {
    uint32_t y;
    asm("cvt.rna.tf32.f32 %0, %1;" : "=r"(y) : "f"(__uint_as_float(x)));
    return y;
}
__device__ __forceinline__ void mma_tf32(float& d0, float& d1, float& d2, float& d3,
                                         uint32_t a0, uint32_t a1, uint32_t a2, uint32_t a3,
                                         uint32_t b0, uint32_t b1) {
    asm volatile("mma.sync.aligned.m16n8k8.row.col.f32.tf32.tf32.f32 "
                 "{%0,%1,%2,%3}, {%4,%5,%6,%7}, {%8,%9}, {%0,%1,%2,%3};"
                 : "+f"(d0), "+f"(d1), "+f"(d2), "+f"(d3)
                 : "r"(a0), "r"(a1), "r"(a2), "r"(a3), "r"(b0), "r"(b1));
}

// ---------------- mma.sync tf32 GEMM ----------------------------------------
// D[BM=128 rows/tile, BN cols/tile] = A[M,K] * B[N,K]^T; C row stride = NR.
// 256 threads: warp grid 2 (m) x 4 (n); warp tile 64 x (BN/4).
// EPI: 0 none, 1 colscale, 2 relu.
template <int BN, int EPI>
__global__ __launch_bounds__(256)
void mm_mma_kernel(const float* __restrict__ A, const float* __restrict__ B,
                   float* __restrict__ C, int K, const float* __restrict__ colscale)
{
    constexpr int BM = 128, BK = 32, S = 3;
    constexpr int NT = BN / 32;           // n-tiles (8 wide) per warp
    constexpr int NP = BN / 64;           // ldmatrix.x4 pairs for B per k-step
    constexpr int A_BYTES = BM * BK * 4;  // 16 KB
    constexpr int B_BYTES = BN * BK * 4;
    constexpr int STAGE   = A_BYTES + B_BYTES;

    extern __shared__ char smem[];
    const uint32_t sb = smem_u32(smem);
    const int tid    = threadIdx.x;
    const int wid    = tid >> 5;
    const int lane   = tid & 31;
    const int warp_m = wid & 1;           // 0..1
    const int warp_n = wid >> 1;          // 0..3

    const int m0 = blockIdx.y * BM;
    const int n0 = blockIdx.x * BN;

    const float* Ab = A + (size_t)m0 * K;
    const float* Bb = B + (size_t)n0 * K;
    const int KT = K >> 5;

    // ldmatrix lane geometry
    const int a_row  = warp_m * 64 + (lane & 15);
    const int a_byte = (lane >> 4) << 4;                          // 0 | 16
    const int b_row  = warp_n * (BN / 4) + ((lane >> 4) << 3) + (lane & 7);
    const int b_byte = (lane & 8) << 1;                           // 0 | 16

    float acc[4][NT][4];
    #pragma unroll
    for (int mt = 0; mt < 4; ++mt)
        #pragma unroll
        for (int nt = 0; nt < NT; ++nt)
            #pragma unroll
            for (int q = 0; q < 4; ++q) acc[mt][nt][q] = 0.0f;

    auto load_stage = [&](int stg) {
        const int slot = stg % S;
        const int k0 = stg << 5;
        const uint32_t as = sb + slot * STAGE;
        const uint32_t bs = as + A_BYTES;
        #pragma unroll
        for (int it = 0; it < 4; ++it) {                    // A: 1024 x 16B
            int idx = tid + it * 256;
            int r = idx >> 3, c = idx & 7;
            cp_async16(as + SWZ(r * 128 + c * 16), Ab + (size_t)r * K + k0 + c * 4);
        }
        #pragma unroll
        for (int it = 0; it < BN / 32; ++it) {              // B
            int idx = tid + it * 256;
            int r = idx >> 3, c = idx & 7;
            cp_async16(bs + SWZ(r * 128 + c * 16), Bb + (size_t)r * K + k0 + c * 4);
        }
    };

    // prologue
    #pragma unroll
    for (int p = 0; p < S - 1; ++p) {
        if (p < KT) load_stage(p);
        cp_commit();
    }

    for (int i = 0; i < KT; ++i) {
        const int ls = i + S - 1;
        if (ls < KT) load_stage(ls);
        cp_commit();
        cp_wait<S - 1>();
        __syncthreads();

        const int slot = i % S;
        const uint32_t as = sb + slot * STAGE;
        const uint32_t bs = as + A_BYTES;

        #pragma unroll
        for (int ks = 0; ks < 4; ++ks) {
            uint32_t af[4][4], bf[NP][4];
            #pragma unroll
            for (int mt = 0; mt < 4; ++mt)
                ldsm_x4(af[mt][0], af[mt][1], af[mt][2], af[mt][3],
                        as + SWZ((a_row + mt * 16) * 128 + ks * 32 + a_byte));
            #pragma unroll
            for (int np = 0; np < NP; ++np)
                ldsm_x4(bf[np][0], bf[np][1], bf[np][2], bf[np][3],
                        bs + SWZ((b_row + np * 16) * 128 + ks * 32 + b_byte));
            // round-to-nearest tf32 (kills truncation bias through the chain)
            #pragma unroll
            for (int mt = 0; mt < 4; ++mt)
                #pragma unroll
                for (int q = 0; q < 4; ++q) af[mt][q] = f2tf32(af[mt][q]);
            #pragma unroll
            for (int np = 0; np < NP; ++np)
                #pragma unroll
                for (int q = 0; q < 4; ++q) bf[np][q] = f2tf32(bf[np][q]);

            #pragma unroll
            for (int mt = 0; mt < 4; ++mt)
                #pragma unroll
                for (int nt = 0; nt < NT; ++nt)
                    mma_tf32(acc[mt][nt][0], acc[mt][nt][1], acc[mt][nt][2], acc[mt][nt][3],
                             af[mt][0], af[mt][1], af[mt][2], af[mt][3],
                             bf[nt >> 1][(nt & 1) * 2], bf[nt >> 1][(nt & 1) * 2 + 1]);
        }
        __syncthreads();
    }

    // epilogue
    const int er = m0 + warp_m * 64 + (lane >> 2);
    const int ec = n0 + warp_n * (BN / 4) + (lane & 3) * 2;
    #pragma unroll
    for (int mt = 0; mt < 4; ++mt) {
        #pragma unroll
        for (int nt = 0; nt < NT; ++nt) {
            const int row = er + mt * 16;
            const int col = ec + nt * 8;
            float v0 = acc[mt][nt][0], v1 = acc[mt][nt][1];
            float v2 = acc[mt][nt][2], v3 = acc[mt][nt][3];
            if (EPI == 1) {
                float2 sc = *(const float2*)&colscale[col];
                v0 *= sc.x; v1 *= sc.y; v2 *= sc.x; v3 *= sc.y;
            }
            if (EPI == 2) {
                v0 = fmaxf(v0, 0.0f); v1 = fmaxf(v1, 0.0f);
                v2 = fmaxf(v2, 0.0f); v3 = fmaxf(v3, 0.0f);
            }
            *(float2*)&C[(size_t)row * NR + col]       = make_float2(v0, v1);
            *(float2*)&C[(size_t)(row + 8) * NR + col] = make_float2(v2, v3);
        }
    }
}

// ---------------- small SIMT kernels ----------------------------------------
__global__ __launch_bounds__(256)
void transpose_w1_kernel(const float* __restrict__ in, float* __restrict__ out)
{
    __shared__ float tile[32][33];
    const int c0 = blockIdx.x * 32;   // j
    const int r0 = blockIdx.y * 32;   // f
    const int tx = threadIdx.x, ty = threadIdx.y;   // 32 x 8
    #pragma unroll
    for (int i = 0; i < 32; i += 8)
        tile[ty + i][tx] = in[(size_t)(r0 + ty + i) * HID + c0 + tx];
    __syncthreads();
    #pragma unroll
    for (int i = 0; i < 32; i += 8)
        out[(size_t)(c0 + ty + i) * FIN + r0 + tx] = tile[tx][ty + i];
}

// sT[j,n] = sum_f w2[f,j] * hT[f,n]   (64 x 8192, K=256)
__global__ __launch_bounds__(256)
void gemm_small_kernel(const float* __restrict__ w2, const float* __restrict__ hT,
                       float* __restrict__ sT)
{
    __shared__ float As[32][64];
    __shared__ float Bs[32][136];     // 136 floats -> 16B-aligned rows for float4
    const int tid = threadIdx.x;
    const int n0 = blockIdx.x * 128;
    const int tj = (tid >> 4) * 4;
    const int tn = (tid & 15) * 8;

    float acc[4][8];
    #pragma unroll
    for (int i = 0; i < 4; ++i)
        #pragma unroll
        for (int j = 0; j < 8; ++j) acc[i][j] = 0.0f;

    for (int f0 = 0; f0 < HID; f0 += 32) {
        #pragma unroll
        for (int it = 0; it < 8; ++it) {
            int idx = tid + it * 256;
            As[idx >> 6][idx & 63] = w2[(size_t)(f0 + (idx >> 6)) * OUTD + (idx & 63)];
        }
        #pragma unroll
        for (int it = 0; it < 4; ++it) {
            int idx = tid + it * 256;
            int f = idx >> 5, n = (idx & 31) * 4;
            *(float4*)&Bs[f][n] = *(const float4*)(hT + (size_t)(f0 + f) * NR + n0 + n);
        }
        __syncthreads();
        #pragma unroll
        for (int kk = 0; kk < 32; ++kk) {
            float a[4], b[8];
            #pragma unroll
            for (int i = 0; i < 4; ++i) a[i] = As[kk][tj + i];
            #pragma unroll
            for (int j = 0; j < 8; ++j) b[j] = Bs[kk][tn + j];
            #pragma unroll
            for (int i = 0; i < 4; ++i)
                #pragma unroll
                for (int j = 0; j < 8; ++j) acc[i][j] = fmaf(a[i], b[j], acc[i][j]);
        }
        __syncthreads();
    }
    #pragma unroll
    for (int i = 0; i < 4; ++i) {
        float* row = sT + (size_t)(tj + i) * NR + n0 + tn;
        *(float4*)row       = make_float4(acc[i][0], acc[i][1], acc[i][2], acc[i][3]);
        *(float4*)(row + 4) = make_float4(acc[i][4], acc[i][5], acc[i][6], acc[i][7]);
    }
}

__global__ __launch_bounds__(256)
void logsoftmax_T_kernel(const float* __restrict__ oT, float* __restrict__ out)
{
    const int m = blockIdx.x * blockDim.x + threadIdx.x;
    if (m >= NR) return;
    float v[OUTD];
    float mx = -1e30f;
    #pragma unroll
    for (int j = 0; j < OUTD; ++j) {
        v[j] = oT[(size_t)j * NR + m];
        mx = fmaxf(mx, v[j]);
    }
    float s = 0.0f;
    #pragma unroll
    for (int j = 0; j < OUTD; ++j) s += expf(v[j] - mx);
    const float lse = mx + logf(s);
    #pragma unroll
    for (int j = 0; j < OUTD; ++j) out[(size_t)m * OUTD + j] = v[j] - lse;
}

// ---------------- kernel_launch ---------------------------------------------
extern "C" void kernel_launch(void* const* d_in, const int* in_sizes, int n_in,
                              void* d_out, int out_size)
{
    (void)in_sizes; (void)n_in; (void)out_size;
    const float* x    = (const float*)d_in[0];
    const float* W    = (const float*)d_in[1];
    const float* Winv = (const float*)d_in[2];
    const float* w1   = (const float*)d_in[3];
    const float* f1   = (const float*)d_in[4];
    const float* w2   = (const float*)d_in[5];
    const float* f2   = (const float*)d_in[6];
    float* out = (float*)d_out;

    float *w1T, *tT, *uT, *hT, *sT, *vT, *oT;
    cudaGetSymbolAddress((void**)&w1T, g_w1T);
    cudaGetSymbolAddress((void**)&tT,  g_tT);
    cudaGetSymbolAddress((void**)&uT,  g_uT);
    cudaGetSymbolAddress((void**)&hT,  g_hT);
    cudaGetSymbolAddress((void**)&sT,  g_sT);
    cudaGetSymbolAddress((void**)&vT,  g_vT);
    cudaGetSymbolAddress((void**)&oT,  g_oT);

    constexpr int SMEM128 = 3 * (128 + 128) * 32 * 4;   // 98304
    constexpr int SMEM64  = 3 * (128 + 64)  * 32 * 4;   // 73728
    cudaFuncSetAttribute(mm_mma_kernel<128, 0>, cudaFuncAttributeMaxDynamicSharedMemorySize, SMEM128);
    cudaFuncSetAttribute(mm_mma_kernel<128, 1>, cudaFuncAttributeMaxDynamicSharedMemorySize, SMEM128);
    cudaFuncSetAttribute(mm_mma_kernel<128, 2>, cudaFuncAttributeMaxDynamicSharedMemorySize, SMEM128);
    cudaFuncSetAttribute(mm_mma_kernel<64, 0>,  cudaFuncAttributeMaxDynamicSharedMemorySize, SMEM64);
    cudaFuncSetAttribute(mm_mma_kernel<64, 1>,  cudaFuncAttributeMaxDynamicSharedMemorySize, SMEM64);

    transpose_w1_kernel<<<dim3(HID / 32, FIN / 32), dim3(32, 8)>>>(w1, w1T);

    // tT = w1T (x) x        [256, 8192], K=512
    mm_mma_kernel<128, 0><<<dim3(NR / 128, 2), 256, SMEM128>>>(w1T, x, tT, FIN, nullptr);
    // uT = (tT (x) Winv)*f1 [256, 8192], K=8192
    mm_mma_kernel<128, 1><<<dim3(NR / 128, 2), 256, SMEM128>>>(tT, Winv, uT, NR, f1);
    // hT = relu(uT (x) W)   [256, 8192], K=8192
    mm_mma_kernel<128, 2><<<dim3(NR / 128, 2), 256, SMEM128>>>(uT, W, hT, NR, nullptr);
    // sT = w2T @ hT         [64 rows, 8192], K=256 (SIMT; rows 64..127 stay 0)
    gemm_small_kernel<<<NR / 128, 256>>>(w2, hT, sT);
    // vT = (sT (x) Winv)*f2 [128 padded, 8192], K=8192
    mm_mma_kernel<64, 1><<<dim3(NR / 64, 1), 256, SMEM64>>>(sT, Winv, vT, NR, f2);
    // oT = vT (x) W         [128 padded, 8192], K=8192
    mm_mma_kernel<64, 0><<<dim3(NR / 64, 1), 256, SMEM64>>>(vT, W, oT, NR, nullptr);

    logsoftmax_T_kernel<<<NR / 256, 256>>>(oT, out);
}

// round 4
// speedup vs baseline: 5.6992x; 1.6040x over previous
#include <cuda_runtime.h>
#include <cstdint>
#include <math.h>

// GWNN on GB300 — mma.sync tf32. Feature-major intermediates (X^T = [d, 8192]).
// Intermediates stored RN-rounded to tf32 at producer epilogue -> no cvt in
// GEMM mainloops (W/Winv raw bits truncate in HW; random-sign error only).
//   tT = w1T (x) x        K=512             (RND)
//   uT = (tT (x) Winv)*f1 K=8192            (RND)
//   hT = relu(uT (x) W)   K=8192            (RND)
//   sT = w2T @ hT         K=256 SIMT        (RND)
//   vT = (sT (x) Winv)*f2 K=8192 splitK4    (combine: *f2, RND)
//   oT = vT (x) W         K=8192 splitK4    (log-softmax sums partials)

#define NR   8192
#define FIN  512
#define HID  256
#define OUTD 64

__device__ float g_w1T[HID * FIN];
__device__ float g_w2T[OUTD * HID];
__device__ float g_tT [HID * NR];
__device__ float g_uT [HID * NR];
__device__ float g_hT [HID * NR];
__device__ float g_sT [OUTD * NR];
__device__ float g_vT [OUTD * NR];
__device__ float g_part[4 * OUTD * NR];   // split-K partials

// ---------------- PTX helpers ----------------------------------------------
__device__ __forceinline__ uint32_t smem_u32(const void* p) {
    uint32_t a;
    asm("{ .reg .u64 t; cvta.to.shared.u64 t, %1; cvt.u32.u64 %0, t; }" : "=r"(a) : "l"(p));
    return a;
}
#define SWZ(x) ((x) ^ (((x) >> 3) & 0x70))

__device__ __forceinline__ void cp_async16(uint32_t dst, const void* src) {
    asm volatile("cp.async.cg.shared.global [%0], [%1], 16;" :: "r"(dst), "l"(src));
}
__device__ __forceinline__ void cp_commit() {
    asm volatile("cp.async.commit_group;" ::: "memory");
}
template <int N>
__device__ __forceinline__ void cp_wait() {
    asm volatile("cp.async.wait_group %0;" :: "n"(N) : "memory");
}
__device__ __forceinline__ void ldsm_x4(uint32_t& r0, uint32_t& r1, uint32_t& r2, uint32_t& r3,
                                        uint32_t addr) {
    asm volatile("ldmatrix.sync.aligned.m8n8.x4.shared.b16 {%0,%1,%2,%3}, [%4];"
                 : "=r"(r0), "=r"(r1), "=r"(r2), "=r"(r3) : "r"(addr));
}
__device__ __forceinline__ float rna_tf32(float x) {
    uint32_t y;
    asm("cvt.rna.tf32.f32 %0, %1;" : "=r"(y) : "f"(x));
    return __uint_as_float(y);
}
__device__ __forceinline__ void mma_tf32(float& d0, float& d1, float& d2, float& d3,
                                         uint32_t a0, uint32_t a1, uint32_t a2, uint32_t a3,
                                         uint32_t b0, uint32_t b1) {
    asm volatile("mma.sync.aligned.m16n8k8.row.col.f32.tf32.tf32.f32 "
                 "{%0,%1,%2,%3}, {%4,%5,%6,%7}, {%8,%9}, {%0,%1,%2,%3};"
                 : "+f"(d0), "+f"(d1), "+f"(d2), "+f"(d3)
                 : "r"(a0), "r"(a1), "r"(a2), "r"(a3), "r"(b0), "r"(b1));
}

// ---------------- mma.sync tf32 GEMM ----------------------------------------
// D[BM, BN] tile of A[M,K] * B[N,K]^T; A,B row-major K-major (stride Kfull),
// C row-major stride NR. Split-K via gridDim.z (Kchunk per z; C += z*OUTD*NR).
// 8 warps: 2 (m) x 4 (n). EPI: 0 none, 1 colscale, 2 relu. RND: tf32-round.
template <int BM, int BN, int EPI, int RND>
__global__ __launch_bounds__(256, 2)
void mm_mma_kernel(const float* __restrict__ A, const float* __restrict__ B,
                   float* __restrict__ C, int Kfull, int Kchunk,
                   const float* __restrict__ colscale)
{
    constexpr int S  = 3;
    constexpr int MT = BM / 32;           // 16-row m-tiles per warp
    constexpr int NT = BN / 32;           // 8-col n-tiles per warp
    constexpr int NP = BN / 64;           // ldmatrix.x4 B loads per k-step
    constexpr int A_BYTES = BM * 128;     // BK=32 floats = 128 B/row
    constexpr int B_BYTES = BN * 128;
    constexpr int STAGE   = A_BYTES + B_BYTES;

    extern __shared__ char smem[];
    const uint32_t sb = smem_u32(smem);
    const int tid    = threadIdx.x;
    const int wid    = tid >> 5;
    const int lane   = tid & 31;
    const int warp_m = wid & 1;
    const int warp_n = wid >> 1;

    const int m0 = blockIdx.y * BM;
    const int n0 = blockIdx.x * BN;
    const int k0 = blockIdx.z * Kchunk;
    C += (size_t)blockIdx.z * OUTD * NR;

    const float* Ab = A + (size_t)m0 * Kfull + k0;
    const float* Bb = B + (size_t)n0 * Kfull + k0;
    const int KT = Kchunk >> 5;

    const int a_row  = warp_m * (BM / 2) + (lane & 15);
    const int a_byte = (lane >> 4) << 4;
    const int b_row  = warp_n * (BN / 4) + ((lane >> 4) << 3) + (lane & 7);
    const int b_byte = (lane & 8) << 1;

    float acc[MT][NT][4];
    #pragma unroll
    for (int mt = 0; mt < MT; ++mt)
        #pragma unroll
        for (int nt = 0; nt < NT; ++nt)
            #pragma unroll
            for (int q = 0; q < 4; ++q) acc[mt][nt][q] = 0.0f;

    auto load_stage = [&](int stg) {
        const int slot = stg % S;
        const int kk0 = stg << 5;
        const uint32_t as = sb + slot * STAGE;
        const uint32_t bs = as + A_BYTES;
        #pragma unroll
        for (int it = 0; it < BM / 32; ++it) {
            int idx = tid + it * 256;
            int r = idx >> 3, c = idx & 7;
            cp_async16(as + SWZ(r * 128 + c * 16), Ab + (size_t)r * Kfull + kk0 + c * 4);
        }
        #pragma unroll
        for (int it = 0; it < BN / 32; ++it) {
            int idx = tid + it * 256;
            int r = idx >> 3, c = idx & 7;
            cp_async16(bs + SWZ(r * 128 + c * 16), Bb + (size_t)r * Kfull + kk0 + c * 4);
        }
    };

    #pragma unroll
    for (int p = 0; p < S - 1; ++p) {
        if (p < KT) load_stage(p);
        cp_commit();
    }

    for (int i = 0; i < KT; ++i) {
        const int ls = i + S - 1;
        if (ls < KT) load_stage(ls);
        cp_commit();
        cp_wait<S - 1>();
        __syncthreads();

        const int slot = i % S;
        const uint32_t as = sb + slot * STAGE;
        const uint32_t bs = as + A_BYTES;

        #pragma unroll
        for (int ks = 0; ks < 4; ++ks) {
            uint32_t af[MT][4], bf[NP][4];
            #pragma unroll
            for (int mt = 0; mt < MT; ++mt)
                ldsm_x4(af[mt][0], af[mt][1], af[mt][2], af[mt][3],
                        as + SWZ((a_row + mt * 16) * 128 + ks * 32 + a_byte));
            #pragma unroll
            for (int np = 0; np < NP; ++np)
                ldsm_x4(bf[np][0], bf[np][1], bf[np][2], bf[np][3],
                        bs + SWZ((b_row + np * 16) * 128 + ks * 32 + b_byte));
            #pragma unroll
            for (int mt = 0; mt < MT; ++mt)
                #pragma unroll
                for (int nt = 0; nt < NT; ++nt)
                    mma_tf32(acc[mt][nt][0], acc[mt][nt][1], acc[mt][nt][2], acc[mt][nt][3],
                             af[mt][0], af[mt][1], af[mt][2], af[mt][3],
                             bf[nt >> 1][(nt & 1) * 2], bf[nt >> 1][(nt & 1) * 2 + 1]);
        }
        __syncthreads();
    }

    // epilogue
    const int er = m0 + warp_m * (BM / 2) + (lane >> 2);
    const int ec = n0 + warp_n * (BN / 4) + (lane & 3) * 2;
    #pragma unroll
    for (int mt = 0; mt < MT; ++mt) {
        #pragma unroll
        for (int nt = 0; nt < NT; ++nt) {
            const int row = er + mt * 16;
            const int col = ec + nt * 8;
            float v0 = acc[mt][nt][0], v1 = acc[mt][nt][1];
            float v2 = acc[mt][nt][2], v3 = acc[mt][nt][3];
            if (EPI == 1) {
                float2 sc = *(const float2*)&colscale[col];
                v0 *= sc.x; v1 *= sc.y; v2 *= sc.x; v3 *= sc.y;
            }
            if (EPI == 2) {
                v0 = fmaxf(v0, 0.0f); v1 = fmaxf(v1, 0.0f);
                v2 = fmaxf(v2, 0.0f); v3 = fmaxf(v3, 0.0f);
            }
            if (RND) {
                v0 = rna_tf32(v0); v1 = rna_tf32(v1);
                v2 = rna_tf32(v2); v3 = rna_tf32(v3);
            }
            *(float2*)&C[(size_t)row * NR + col]       = make_float2(v0, v1);
            *(float2*)&C[(size_t)(row + 8) * NR + col] = make_float2(v2, v3);
        }
    }
}

// ---------------- small kernels ---------------------------------------------
// out[c, r] = rna(in[r, c]),  in is [R, C]
__global__ __launch_bounds__(256)
void transpose_rna_kernel(const float* __restrict__ in, float* __restrict__ out,
                          int R, int C)
{
    __shared__ float tile[32][33];
    const int c0 = blockIdx.x * 32;
    const int r0 = blockIdx.y * 32;
    const int tx = threadIdx.x, ty = threadIdx.y;   // 32 x 8
    #pragma unroll
    for (int i = 0; i < 32; i += 8)
        tile[ty + i][tx] = in[(size_t)(r0 + ty + i) * C + c0 + tx];
    __syncthreads();
    #pragma unroll
    for (int i = 0; i < 32; i += 8)
        out[(size_t)(c0 + ty + i) * R + r0 + tx] = rna_tf32(tile[tx][ty + i]);
}

// sT[j,n] = rna( sum_f w2[f,j] * hT[f,n] )   (64 x 8192, K=256) — SIMT
// (hT is feature-major so the "B" operand here is column-strided; read direct)
__global__ __launch_bounds__(256)
void gemm_small_kernel(const float* __restrict__ w2, const float* __restrict__ hT,
                       float* __restrict__ sT)
{
    __shared__ float As[32][64];
    __shared__ float Bs[32][136];
    const int tid = threadIdx.x;
    const int n0 = blockIdx.x * 128;
    const int tj = (tid >> 4) * 4;
    const int tn = (tid & 15) * 8;

    float acc[4][8];
    #pragma unroll
    for (int i = 0; i < 4; ++i)
        #pragma unroll
        for (int j = 0; j < 8; ++j) acc[i][j] = 0.0f;

    for (int f0 = 0; f0 < HID; f0 += 32) {
        #pragma unroll
        for (int it = 0; it < 8; ++it) {
            int idx = tid + it * 256;
            As[idx >> 6][idx & 63] = w2[(size_t)(f0 + (idx >> 6)) * OUTD + (idx & 63)];
        }
        #pragma unroll
        for (int it = 0; it < 4; ++it) {
            int idx = tid + it * 256;
            int f = idx >> 5, n = (idx & 31) * 4;
            *(float4*)&Bs[f][n] = *(const float4*)(hT + (size_t)(f0 + f) * NR + n0 + n);
        }
        __syncthreads();
        #pragma unroll
        for (int kk = 0; kk < 32; ++kk) {
            float a[4], b[8];
            #pragma unroll
            for (int i = 0; i < 4; ++i) a[i] = As[kk][tj + i];
            #pragma unroll
            for (int j = 0; j < 8; ++j) b[j] = Bs[kk][tn + j];
            #pragma unroll
            for (int i = 0; i < 4; ++i)
                #pragma unroll
                for (int j = 0; j < 8; ++j) acc[i][j] = fmaf(a[i], b[j], acc[i][j]);
        }
        __syncthreads();
    }
    #pragma unroll
    for (int i = 0; i < 4; ++i) {
        float* row = sT + (size_t)(tj + i) * NR + n0 + tn;
        #pragma unroll
        for (int j = 0; j < 8; ++j) row[j] = rna_tf32(acc[i][j]);
    }
}

// vT = rna( (sum_z part_z) * f2[col] )
__global__ __launch_bounds__(256)
void combine_vT_kernel(const float* __restrict__ P, const float* __restrict__ f2,
                       float* __restrict__ vT)
{
    constexpr size_t CH = (size_t)OUTD * NR;
    const size_t idx = (size_t)blockIdx.x * 256 + threadIdx.x;
    const int n = (int)(idx & (NR - 1));
    float v = P[idx] + P[idx + CH] + P[idx + 2 * CH] + P[idx + 3 * CH];
    vT[idx] = rna_tf32(v * f2[n]);
}

// out[m, j] = (sum_z P_z[j, m]) - logsumexp_j
__global__ __launch_bounds__(256)
void logsoftmax_part_kernel(const float* __restrict__ P, float* __restrict__ out)
{
    constexpr size_t CH = (size_t)OUTD * NR;
    const int m = blockIdx.x * blockDim.x + threadIdx.x;
    if (m >= NR) return;
    float v[OUTD];
    float mx = -1e30f;
    #pragma unroll
    for (int j = 0; j < OUTD; ++j) {
        const size_t base = (size_t)j * NR + m;
        v[j] = P[base] + P[base + CH] + P[base + 2 * CH] + P[base + 3 * CH];
        mx = fmaxf(mx, v[j]);
    }
    float s = 0.0f;
    #pragma unroll
    for (int j = 0; j < OUTD; ++j) s += expf(v[j] - mx);
    const float lse = mx + logf(s);
    #pragma unroll
    for (int j = 0; j < OUTD; ++j) out[(size_t)m * OUTD + j] = v[j] - lse;
}

// ---------------- kernel_launch ---------------------------------------------
extern "C" void kernel_launch(void* const* d_in, const int* in_sizes, int n_in,
                              void* d_out, int out_size)
{
    (void)in_sizes; (void)n_in; (void)out_size;
    const float* x    = (const float*)d_in[0];
    const float* W    = (const float*)d_in[1];
    const float* Winv = (const float*)d_in[2];
    const float* w1   = (const float*)d_in[3];
    const float* f1   = (const float*)d_in[4];
    const float* w2   = (const float*)d_in[5];
    const float* f2   = (const float*)d_in[6];
    float* out = (float*)d_out;

    float *w1T, *w2T, *tT, *uT, *hT, *sT, *vT, *part;
    cudaGetSymbolAddress((void**)&w1T,  g_w1T);
    cudaGetSymbolAddress((void**)&w2T,  g_w2T);
    cudaGetSymbolAddress((void**)&tT,   g_tT);
    cudaGetSymbolAddress((void**)&uT,   g_uT);
    cudaGetSymbolAddress((void**)&hT,   g_hT);
    cudaGetSymbolAddress((void**)&sT,   g_sT);
    cudaGetSymbolAddress((void**)&vT,   g_vT);
    cudaGetSymbolAddress((void**)&part, g_part);

    constexpr int SMEM = 3 * (64 + 128) * 128;   // 73728
    cudaFuncSetAttribute(mm_mma_kernel<64, 128, 0, 1>, cudaFuncAttributeMaxDynamicSharedMemorySize, SMEM);
    cudaFuncSetAttribute(mm_mma_kernel<64, 128, 1, 1>, cudaFuncAttributeMaxDynamicSharedMemorySize, SMEM);
    cudaFuncSetAttribute(mm_mma_kernel<64, 128, 2, 1>, cudaFuncAttributeMaxDynamicSharedMemorySize, SMEM);
    cudaFuncSetAttribute(mm_mma_kernel<64, 128, 0, 0>, cudaFuncAttributeMaxDynamicSharedMemorySize, SMEM);

    transpose_rna_kernel<<<dim3(HID / 32, FIN / 32), dim3(32, 8)>>>(w1, w1T, FIN, HID);
    transpose_rna_kernel<<<dim3(OUTD / 32, HID / 32), dim3(32, 8)>>>(w2, w2T, HID, OUTD);

    // tT = w1T (x) x            [256, 8192], K=512
    mm_mma_kernel<64, 128, 0, 1><<<dim3(NR / 128, HID / 64, 1), 256, SMEM>>>(w1T, x, tT, FIN, FIN, nullptr);
    // uT = (tT (x) Winv) * f1   [256, 8192], K=8192
    mm_mma_kernel<64, 128, 1, 1><<<dim3(NR / 128, HID / 64, 1), 256, SMEM>>>(tT, Winv, uT, NR, NR, f1);
    // hT = relu(uT (x) W)       [256, 8192], K=8192
    mm_mma_kernel<64, 128, 2, 1><<<dim3(NR / 128, HID / 64, 1), 256, SMEM>>>(uT, W, hT, NR, NR, nullptr);
    // sT = w2T @ hT             [64, 8192], K=256 (SIMT; hT column-strided)
    gemm_small_kernel<<<NR / 128, 256>>>(w2, hT, sT);
    // vT partials: sT (x) Winv  [64, 8192], K=8192, split-K 4
    mm_mma_kernel<64, 128, 0, 0><<<dim3(NR / 128, 1, 4), 256, SMEM>>>(sT, Winv, part, NR, NR / 4, nullptr);
    combine_vT_kernel<<<(OUTD * NR) / 256, 256>>>(part, f2, vT);
    // oT partials: vT (x) W     [64, 8192], K=8192, split-K 4
    mm_mma_kernel<64, 128, 0, 0><<<dim3(NR / 128, 1, 4), 256, SMEM>>>(vT, W, part, NR, NR / 4, nullptr);
    // out = log_softmax(sum of partials, axis=features)
    logsoftmax_part_kernel<<<NR / 256, 256>>>(part, out);
}

// round 5
// speedup vs baseline: 5.8451x; 1.0256x over previous
#include <cuda_runtime.h>
#include <cstdint>
#include <math.h>

// GWNN on GB300 — mma.sync tf32, multistage single-barrier pipeline.
// Feature-major intermediates (X^T = [d, 8192]); intermediates RN-rounded to
// tf32 at producer epilogue (no cvt in mainloops).
//   tT = w1T (x) x        K=512             (RND)
//   uT = (tT (x) Winv)*f1 K=8192            (RND)
//   hT = relu(uT (x) W)   K=8192            (RND)
//   sT = w2T @ hT         K=256 SIMT        (RND)
//   vT = (sT (x) Winv)*f2 K=8192 splitK4    (combine: *f2, RND)
//   oT = vT (x) W         K=8192 splitK4    (log-softmax sums partials)

#define NR   8192
#define FIN  512
#define HID  256
#define OUTD 64

__device__ float g_w1T[HID * FIN];
__device__ float g_w2T[OUTD * HID];
__device__ float g_tT [HID * NR];
__device__ float g_uT [HID * NR];
__device__ float g_hT [HID * NR];
__device__ float g_sT [OUTD * NR];
__device__ float g_vT [OUTD * NR];
__device__ float g_part[4 * OUTD * NR];   // split-K partials

// ---------------- PTX helpers ----------------------------------------------
__device__ __forceinline__ uint32_t smem_u32(const void* p) {
    uint32_t a;
    asm("{ .reg .u64 t; cvta.to.shared.u64 t, %1; cvt.u32.u64 %0, t; }" : "=r"(a) : "l"(p));
    return a;
}
#define SWZ(x) ((x) ^ (((x) >> 3) & 0x70))

__device__ __forceinline__ void cp_async16(uint32_t dst, const void* src) {
    asm volatile("cp.async.cg.shared.global [%0], [%1], 16;" :: "r"(dst), "l"(src));
}
__device__ __forceinline__ void cp_commit() {
    asm volatile("cp.async.commit_group;" ::: "memory");
}
template <int N>
__device__ __forceinline__ void cp_wait() {
    asm volatile("cp.async.wait_group %0;" :: "n"(N) : "memory");
}
__device__ __forceinline__ void ldsm_x4(uint32_t& r0, uint32_t& r1, uint32_t& r2, uint32_t& r3,
                                        uint32_t addr) {
    asm volatile("ldmatrix.sync.aligned.m8n8.x4.shared.b16 {%0,%1,%2,%3}, [%4];"
                 : "=r"(r0), "=r"(r1), "=r"(r2), "=r"(r3) : "r"(addr));
}
__device__ __forceinline__ float rna_tf32(float x) {
    uint32_t y;
    asm("cvt.rna.tf32.f32 %0, %1;" : "=r"(y) : "f"(x));
    return __uint_as_float(y);
}
__device__ __forceinline__ void mma_tf32(float& d0, float& d1, float& d2, float& d3,
                                         uint32_t a0, uint32_t a1, uint32_t a2, uint32_t a3,
                                         uint32_t b0, uint32_t b1) {
    asm volatile("mma.sync.aligned.m16n8k8.row.col.f32.tf32.tf32.f32 "
                 "{%0,%1,%2,%3}, {%4,%5,%6,%7}, {%8,%9}, {%0,%1,%2,%3};"
                 : "+f"(d0), "+f"(d1), "+f"(d2), "+f"(d3)
                 : "r"(a0), "r"(a1), "r"(a2), "r"(a3), "r"(b0), "r"(b1));
}

// ---------------- mma.sync tf32 GEMM ----------------------------------------
// D[BM, BN] tile of A[M,K] * B[N,K]^T; A,B row-major K-major (stride Kfull),
// C row-major stride NR. Split-K via gridDim.z (Kchunk per z; C += z*OUTD*NR).
// 8 warps: 2 (m) x 4 (n). EPI: 0 none, 1 colscale, 2 relu. RND: tf32-round.
// Multistage S=4, ONE __syncthreads per K32 iteration.
template <int BM, int BN, int EPI, int RND>
__global__ __launch_bounds__(256, 2)
void mm_mma_kernel(const float* __restrict__ A, const float* __restrict__ B,
                   float* __restrict__ C, int Kfull, int Kchunk,
                   const float* __restrict__ colscale)
{
    constexpr int S  = 4;
    constexpr int MT = BM / 32;           // 16-row m-tiles per warp
    constexpr int NT = BN / 32;           // 8-col n-tiles per warp
    constexpr int NP = BN / 64;           // ldmatrix.x4 B loads per k-step
    constexpr int AI = BM / 32;           // A cp.async iters (256 thr, 16B each)
    constexpr int BI = BN / 32;           // B cp.async iters
    constexpr int A_BYTES = BM * 128;     // BK=32 floats = 128 B/row
    constexpr int B_BYTES = BN * 128;
    constexpr int STAGE   = A_BYTES + B_BYTES;

    extern __shared__ char smem[];
    const uint32_t sb = smem_u32(smem);
    const int tid    = threadIdx.x;
    const int wid    = tid >> 5;
    const int lane   = tid & 31;
    const int warp_m = wid & 1;
    const int warp_n = wid >> 1;

    const int m0 = blockIdx.y * BM;
    const int n0 = blockIdx.x * BN;
    const int k0 = blockIdx.z * Kchunk;
    C += (size_t)blockIdx.z * OUTD * NR;

    const float* Ab = A + (size_t)m0 * Kfull + k0;
    const float* Bb = B + (size_t)n0 * Kfull + k0;
    const int KT = Kchunk >> 5;

    // ---- hoisted loader addressing (stage-invariant) ----
    const int lr = tid >> 3;              // 0..31
    const int lc = tid & 7;               // 0..7
    const float* aP[AI];
    const float* bP[BI];
    uint32_t aD[AI], bD[BI];
    #pragma unroll
    for (int it = 0; it < AI; ++it) {
        const int r = lr + it * 32;
        aP[it] = Ab + (size_t)r * Kfull + lc * 4;
        aD[it] = SWZ(r * 128 + lc * 16);
    }
    #pragma unroll
    for (int it = 0; it < BI; ++it) {
        const int r = lr + it * 32;
        bP[it] = Bb + (size_t)r * Kfull + lc * 4;
        bD[it] = SWZ(r * 128 + lc * 16);
    }

    // ---- hoisted ldmatrix addressing ----
    const int a_row  = warp_m * (BM / 2) + (lane & 15);
    const int a_byte = (lane >> 4) << 4;
    const int b_row  = warp_n * (BN / 4) + ((lane >> 4) << 3) + (lane & 7);
    const int b_byte = (lane & 8) << 1;

    float acc[MT][NT][4];
    #pragma unroll
    for (int mt = 0; mt < MT; ++mt)
        #pragma unroll
        for (int nt = 0; nt < NT; ++nt)
            #pragma unroll
            for (int q = 0; q < 4; ++q) acc[mt][nt][q] = 0.0f;

    auto load_stage = [&](int stg) {
        const uint32_t as = sb + (stg % S) * STAGE;
        const uint32_t bs = as + A_BYTES;
        const int koff = stg << 5;
        #pragma unroll
        for (int it = 0; it < AI; ++it)
            cp_async16(as + aD[it], aP[it] + koff);
        #pragma unroll
        for (int it = 0; it < BI; ++it)
            cp_async16(bs + bD[it], bP[it] + koff);
    };

    // prologue: stages 0..S-2
    #pragma unroll
    for (int p = 0; p < S - 1; ++p) {
        if (p < KT) load_stage(p);
        cp_commit();
    }

    for (int i = 0; i < KT; ++i) {
        cp_wait<S - 2>();        // stage i landed
        __syncthreads();         // publish stage i; slot (i-1)%S drained by all
        if (i + S - 1 < KT) load_stage(i + S - 1);
        cp_commit();

        const uint32_t as = sb + (i % S) * STAGE;
        const uint32_t bs = as + A_BYTES;

        #pragma unroll
        for (int ks = 0; ks < 4; ++ks) {
            uint32_t af[MT][4], bf[NP][4];
            #pragma unroll
            for (int mt = 0; mt < MT; ++mt)
                ldsm_x4(af[mt][0], af[mt][1], af[mt][2], af[mt][3],
                        as + SWZ((a_row + mt * 16) * 128 + ks * 32 + a_byte));
            #pragma unroll
            for (int np = 0; np < NP; ++np)
                ldsm_x4(bf[np][0], bf[np][1], bf[np][2], bf[np][3],
                        bs + SWZ((b_row + np * 16) * 128 + ks * 32 + b_byte));
            #pragma unroll
            for (int mt = 0; mt < MT; ++mt)
                #pragma unroll
                for (int nt = 0; nt < NT; ++nt)
                    mma_tf32(acc[mt][nt][0], acc[mt][nt][1], acc[mt][nt][2], acc[mt][nt][3],
                             af[mt][0], af[mt][1], af[mt][2], af[mt][3],
                             bf[nt >> 1][(nt & 1) * 2], bf[nt >> 1][(nt & 1) * 2 + 1]);
        }
    }

    // epilogue
    const int er = m0 + warp_m * (BM / 2) + (lane >> 2);
    const int ec = n0 + warp_n * (BN / 4) + (lane & 3) * 2;
    #pragma unroll
    for (int mt = 0; mt < MT; ++mt) {
        #pragma unroll
        for (int nt = 0; nt < NT; ++nt) {
            const int row = er + mt * 16;
            const int col = ec + nt * 8;
            float v0 = acc[mt][nt][0], v1 = acc[mt][nt][1];
            float v2 = acc[mt][nt][2], v3 = acc[mt][nt][3];
            if (EPI == 1) {
                float2 sc = *(const float2*)&colscale[col];
                v0 *= sc.x; v1 *= sc.y; v2 *= sc.x; v3 *= sc.y;
            }
            if (EPI == 2) {
                v0 = fmaxf(v0, 0.0f); v1 = fmaxf(v1, 0.0f);
                v2 = fmaxf(v2, 0.0f); v3 = fmaxf(v3, 0.0f);
            }
            if (RND) {
                v0 = rna_tf32(v0); v1 = rna_tf32(v1);
                v2 = rna_tf32(v2); v3 = rna_tf32(v3);
            }
            *(float2*)&C[(size_t)row * NR + col]       = make_float2(v0, v1);
            *(float2*)&C[(size_t)(row + 8) * NR + col] = make_float2(v2, v3);
        }
    }
}

// ---------------- small kernels ---------------------------------------------
// out[c, r] = rna(in[r, c]),  in is [R, C]
__global__ __launch_bounds__(256)
void transpose_rna_kernel(const float* __restrict__ in, float* __restrict__ out,
                          int R, int C)
{
    __shared__ float tile[32][33];
    const int c0 = blockIdx.x * 32;
    const int r0 = blockIdx.y * 32;
    const int tx = threadIdx.x, ty = threadIdx.y;   // 32 x 8
    #pragma unroll
    for (int i = 0; i < 32; i += 8)
        tile[ty + i][tx] = in[(size_t)(r0 + ty + i) * C + c0 + tx];
    __syncthreads();
    #pragma unroll
    for (int i = 0; i < 32; i += 8)
        out[(size_t)(c0 + ty + i) * R + r0 + tx] = rna_tf32(tile[tx][ty + i]);
}

// sT[j,n] = rna( sum_f w2[f,j] * hT[f,n] )   (64 x 8192, K=256) — SIMT
__global__ __launch_bounds__(256)
void gemm_small_kernel(const float* __restrict__ w2, const float* __restrict__ hT,
                       float* __restrict__ sT)
{
    __shared__ float As[32][64];
    __shared__ float Bs[32][136];
    const int tid = threadIdx.x;
    const int n0 = blockIdx.x * 128;
    const int tj = (tid >> 4) * 4;
    const int tn = (tid & 15) * 8;

    float acc[4][8];
    #pragma unroll
    for (int i = 0; i < 4; ++i)
        #pragma unroll
        for (int j = 0; j < 8; ++j) acc[i][j] = 0.0f;

    for (int f0 = 0; f0 < HID; f0 += 32) {
        #pragma unroll
        for (int it = 0; it < 8; ++it) {
            int idx = tid + it * 256;
            As[idx >> 6][idx & 63] = w2[(size_t)(f0 + (idx >> 6)) * OUTD + (idx & 63)];
        }
        #pragma unroll
        for (int it = 0; it < 4; ++it) {
            int idx = tid + it * 256;
            int f = idx >> 5, n = (idx & 31) * 4;
            *(float4*)&Bs[f][n] = *(const float4*)(hT + (size_t)(f0 + f) * NR + n0 + n);
        }
        __syncthreads();
        #pragma unroll
        for (int kk = 0; kk < 32; ++kk) {
            float a[4], b[8];
            #pragma unroll
            for (int i = 0; i < 4; ++i) a[i] = As[kk][tj + i];
            #pragma unroll
            for (int j = 0; j < 8; ++j) b[j] = Bs[kk][tn + j];
            #pragma unroll
            for (int i = 0; i < 4; ++i)
                #pragma unroll
                for (int j = 0; j < 8; ++j) acc[i][j] = fmaf(a[i], b[j], acc[i][j]);
        }
        __syncthreads();
    }
    #pragma unroll
    for (int i = 0; i < 4; ++i) {
        float* row = sT + (size_t)(tj + i) * NR + n0 + tn;
        #pragma unroll
        for (int j = 0; j < 8; ++j) row[j] = rna_tf32(acc[i][j]);
    }
}

// vT = rna( (sum_z part_z) * f2[col] )
__global__ __launch_bounds__(256)
void combine_vT_kernel(const float* __restrict__ P, const float* __restrict__ f2,
                       float* __restrict__ vT)
{
    constexpr size_t CH = (size_t)OUTD * NR;
    const size_t idx = (size_t)blockIdx.x * 256 + threadIdx.x;
    const int n = (int)(idx & (NR - 1));
    float v = P[idx] + P[idx + CH] + P[idx + 2 * CH] + P[idx + 3 * CH];
    vT[idx] = rna_tf32(v * f2[n]);
}

// out[m, j] = (sum_z P_z[j, m]) - logsumexp_j
__global__ __launch_bounds__(256)
void logsoftmax_part_kernel(const float* __restrict__ P, float* __restrict__ out)
{
    constexpr size_t CH = (size_t)OUTD * NR;
    const int m = blockIdx.x * blockDim.x + threadIdx.x;
    if (m >= NR) return;
    float v[OUTD];
    float mx = -1e30f;
    #pragma unroll
    for (int j = 0; j < OUTD; ++j) {
        const size_t base = (size_t)j * NR + m;
        v[j] = P[base] + P[base + CH] + P[base + 2 * CH] + P[base + 3 * CH];
        mx = fmaxf(mx, v[j]);
    }
    float s = 0.0f;
    #pragma unroll
    for (int j = 0; j < OUTD; ++j) s += expf(v[j] - mx);
    const float lse = mx + logf(s);
    #pragma unroll
    for (int j = 0; j < OUTD; ++j) out[(size_t)m * OUTD + j] = v[j] - lse;
}

// ---------------- kernel_launch ---------------------------------------------
extern "C" void kernel_launch(void* const* d_in, const int* in_sizes, int n_in,
                              void* d_out, int out_size)
{
    (void)in_sizes; (void)n_in; (void)out_size;
    const float* x    = (const float*)d_in[0];
    const float* W    = (const float*)d_in[1];
    const float* Winv = (const float*)d_in[2];
    const float* w1   = (const float*)d_in[3];
    const float* f1   = (const float*)d_in[4];
    const float* w2   = (const float*)d_in[5];
    const float* f2   = (const float*)d_in[6];
    float* out = (float*)d_out;

    float *w1T, *w2T, *tT, *uT, *hT, *sT, *vT, *part;
    cudaGetSymbolAddress((void**)&w1T,  g_w1T);
    cudaGetSymbolAddress((void**)&w2T,  g_w2T);
    cudaGetSymbolAddress((void**)&tT,   g_tT);
    cudaGetSymbolAddress((void**)&uT,   g_uT);
    cudaGetSymbolAddress((void**)&hT,   g_hT);
    cudaGetSymbolAddress((void**)&sT,   g_sT);
    cudaGetSymbolAddress((void**)&vT,   g_vT);
    cudaGetSymbolAddress((void**)&part, g_part);

    constexpr int SMEM = 4 * (64 + 128) * 128;   // 98304 (S=4 stages)
    cudaFuncSetAttribute(mm_mma_kernel<64, 128, 0, 1>, cudaFuncAttributeMaxDynamicSharedMemorySize, SMEM);
    cudaFuncSetAttribute(mm_mma_kernel<64, 128, 1, 1>, cudaFuncAttributeMaxDynamicSharedMemorySize, SMEM);
    cudaFuncSetAttribute(mm_mma_kernel<64, 128, 2, 1>, cudaFuncAttributeMaxDynamicSharedMemorySize, SMEM);
    cudaFuncSetAttribute(mm_mma_kernel<64, 128, 0, 0>, cudaFuncAttributeMaxDynamicSharedMemorySize, SMEM);

    transpose_rna_kernel<<<dim3(HID / 32, FIN / 32), dim3(32, 8)>>>(w1, w1T, FIN, HID);
    transpose_rna_kernel<<<dim3(OUTD / 32, HID / 32), dim3(32, 8)>>>(w2, w2T, HID, OUTD);

    // tT = w1T (x) x            [256, 8192], K=512
    mm_mma_kernel<64, 128, 0, 1><<<dim3(NR / 128, HID / 64, 1), 256, SMEM>>>(w1T, x, tT, FIN, FIN, nullptr);
    // uT = (tT (x) Winv) * f1   [256, 8192], K=8192
    mm_mma_kernel<64, 128, 1, 1><<<dim3(NR / 128, HID / 64, 1), 256, SMEM>>>(tT, Winv, uT, NR, NR, f1);
    // hT = relu(uT (x) W)       [256, 8192], K=8192
    mm_mma_kernel<64, 128, 2, 1><<<dim3(NR / 128, HID / 64, 1), 256, SMEM>>>(uT, W, hT, NR, NR, nullptr);
    // sT = w2T @ hT             [64, 8192], K=256 (SIMT)
    gemm_small_kernel<<<NR / 128, 256>>>(w2, hT, sT);
    // vT partials: sT (x) Winv  [64, 8192], K=8192, split-K 4
    mm_mma_kernel<64, 128, 0, 0><<<dim3(NR / 128, 1, 4), 256, SMEM>>>(sT, Winv, part, NR, NR / 4, nullptr);
    combine_vT_kernel<<<(OUTD * NR) / 256, 256>>>(part, f2, vT);
    // oT partials: vT (x) W     [64, 8192], K=8192, split-K 4
    mm_mma_kernel<64, 128, 0, 0><<<dim3(NR / 128, 1, 4), 256, SMEM>>>(vT, W, part, NR, NR / 4, nullptr);
    // out = log_softmax(sum of partials, axis=features)
    logsoftmax_part_kernel<<<NR / 256, 256>>>(part, out);
}